// round 5
// baseline (speedup 1.0000x reference)
#include <cuda_runtime.h>
#include <math.h>

#define NTHREADS 1024
#define BT 16
#define HD 512
#define ST 20   // column stride (floats) for column-major activations; 80B keeps 16B alignment

typedef unsigned long long ull;

struct Smem {
    float hA[HD * ST];   // column-major: hA[c*ST + row]
    float hB[HD * ST];
    ull red[8][HD];      // k-split reduction buffer: red[pair][col]
    float in[16 * ST];   // column-major MLP input
    float x[BT][12];
    float fn[BT][3];
    float part[96];
    float Im[9];
    float Iinv[9];
};

__device__ __forceinline__ float leaky(float v) { return v >= 0.f ? v : 0.01f * v; }

// packed f32x2 ops (sm_100+)
__device__ __forceinline__ ull fma2(ull a, ull b, ull c) {
    ull d;
    asm("fma.rn.f32x2 %0, %1, %2, %3;" : "=l"(d) : "l"(a), "l"(b), "l"(c));
    return d;
}
__device__ __forceinline__ ull add2(ull a, ull b) {
    ull d;
    asm("add.rn.f32x2 %0, %1, %2;" : "=l"(d) : "l"(a), "l"(b));
    return d;
}
__device__ __forceinline__ ull pack2(float x) {
    ull r;
    asm("mov.b64 %0, {%1, %1};" : "=l"(r) : "f"(x));
    return r;
}
__device__ __forceinline__ float2 unpack2(ull v) {
    float2 f;
    asm("mov.b64 {%0, %1}, %2;" : "=f"(f.x), "=f"(f.y) : "l"(v));
    return f;
}

// K -> 512 layer, column-major activations, K split across two thread groups.
// si: column-major input  [K][rows]   (si[k*ST + row])
// so: column-major output [512][rows] (so[c*ST + row])
// tx in [0,512) owns output column tx (all 16 rows, as 8 row-pairs).
// kh in {0,1}: sums k in [kh*K/2, (kh+1)*K/2). kh=1 spills partials to S.red,
// kh=0 reduces, adds bias, applies leaky, stores.
template <int K>
__device__ __forceinline__ void layer_col(Smem& S,
                                          const float* __restrict__ si,
                                          float* __restrict__ so,
                                          const float* __restrict__ W,
                                          const float* __restrict__ bv,
                                          int tx, int kh) {
    constexpr int KH = K / 2;
    ull acc[8];
#pragma unroll
    for (int p = 0; p < 8; p++) acc[p] = 0ULL;

    const float* wp = W + (size_t)kh * KH * HD + tx;
    const float* ap = si + kh * KH * ST;
#pragma unroll 4
    for (int k = 0; k < KH; k++) {
        ull w = pack2(wp[0]);
        wp += HD;
        ulonglong2 a0 = *reinterpret_cast<const ulonglong2*>(ap);
        ulonglong2 a1 = *reinterpret_cast<const ulonglong2*>(ap + 4);
        ulonglong2 a2 = *reinterpret_cast<const ulonglong2*>(ap + 8);
        ulonglong2 a3 = *reinterpret_cast<const ulonglong2*>(ap + 12);
        ap += ST;
        acc[0] = fma2(a0.x, w, acc[0]);
        acc[1] = fma2(a0.y, w, acc[1]);
        acc[2] = fma2(a1.x, w, acc[2]);
        acc[3] = fma2(a1.y, w, acc[3]);
        acc[4] = fma2(a2.x, w, acc[4]);
        acc[5] = fma2(a2.y, w, acc[5]);
        acc[6] = fma2(a3.x, w, acc[6]);
        acc[7] = fma2(a3.y, w, acc[7]);
    }

    if (kh == 1) {
#pragma unroll
        for (int p = 0; p < 8; p++) S.red[p][tx] = acc[p];
    }
    __syncthreads();
    if (kh == 0) {
        const float b = bv[tx];
        float* o = so + tx * ST;
#pragma unroll
        for (int p = 0; p < 8; p += 2) {
            ull s0 = add2(acc[p], S.red[p][tx]);
            ull s1 = add2(acc[p + 1], S.red[p + 1][tx]);
            float2 v0 = unpack2(s0);
            float2 v1 = unpack2(s1);
            float4 ov;
            ov.x = leaky(v0.x + b);
            ov.y = leaky(v0.y + b);
            ov.z = leaky(v1.x + b);
            ov.w = leaky(v1.y + b);
            *reinterpret_cast<float4*>(o + p * 2) = ov;
        }
    }
    __syncthreads();
}

// Rigid-body derivatives, M (moments) == 0.
__device__ __forceinline__ void derivs(const float x[12], float F0, float F1, float F2,
                                       const float Im[9], const float Iv[9], float dx[12]) {
    float V0 = x[3], V1 = x[4], V2 = x[5];
    float phi = x[6], th = x[7], ps = x[8];
    float w0 = x[9], w1 = x[10], w2 = x[11];
    float cph = cosf(phi), sph = sinf(phi);
    float cth = cosf(th), sth = sinf(th);
    float cps = cosf(ps), sps = sinf(ps);

    dx[0] = (cth * cps) * V0 + (sph * sth * cps - cph * sps) * V1 + (cph * sth * cps + sph * sps) * V2;
    dx[1] = (cth * sps) * V0 + (sph * sth * sps + cph * cps) * V1 + (cph * sth * sps - sph * cps) * V2;
    dx[2] = (-sth) * V0 + (sph * cth) * V1 + (cph * cth) * V2;

    dx[3] = F0 / 1.5f - (w1 * V2 - w2 * V1);
    dx[4] = F1 / 1.5f - (w2 * V0 - w0 * V2);
    dx[5] = F2 / 1.5f - (w0 * V1 - w1 * V0);

    float tth = tanf(th);
    float cthc = fmaxf(cth, 1e-6f);
    float ic = 1.0f / cthc;
    dx[6] = w0 + sph * tth * w1 + cph * tth * w2;
    dx[7] = cph * w1 - sph * w2;
    dx[8] = (sph * ic) * w1 + (cph * ic) * w2;

    float Iw0 = Im[0] * w0 + Im[1] * w1 + Im[2] * w2;
    float Iw1 = Im[3] * w0 + Im[4] * w1 + Im[5] * w2;
    float Iw2 = Im[6] * w0 + Im[7] * w1 + Im[8] * w2;
    float c0 = w1 * Iw2 - w2 * Iw1;
    float c1 = w2 * Iw0 - w0 * Iw2;
    float c2 = w0 * Iw1 - w1 * Iw0;
    dx[9]  = -(Iv[0] * c0 + Iv[1] * c1 + Iv[2] * c2);
    dx[10] = -(Iv[3] * c0 + Iv[4] * c1 + Iv[5] * c2);
    dx[11] = -(Iv[6] * c0 + Iv[7] * c1 + Iv[8] * c2);
}

extern "C" __global__ void __launch_bounds__(NTHREADS, 1)
wm_rollout(const float* __restrict__ x_t, const float* __restrict__ act,
           const float* __restrict__ Imat_g,
           const float* __restrict__ W0, const float* __restrict__ b0,
           const float* __restrict__ W1, const float* __restrict__ b1,
           const float* __restrict__ W2, const float* __restrict__ b2,
           const float* __restrict__ W3, const float* __restrict__ b3,
           const int* __restrict__ seqp, float* __restrict__ out, int Bn) {
    extern __shared__ char smc[];
    Smem& S = *reinterpret_cast<Smem*>(smc);
    const int tid = threadIdx.x;
    const int tx = tid & 511;      // output column
    const int kh = tid >> 9;       // k-half

    const int T = seqp[0];
    const int steps = T - 1;
    float* outF = out;                                   // [B, 6, T-1]
    float* outX = out + (size_t)Bn * 6 * steps;          // [B, 12, T]

    if (tid == 0) {
        float a = Imat_g[0], b = Imat_g[1], c = Imat_g[2];
        float d = Imat_g[3], e = Imat_g[4], f = Imat_g[5];
        float g = Imat_g[6], h = Imat_g[7], i = Imat_g[8];
        float A = e * i - f * h;
        float Bc = -(d * i - f * g);
        float C = d * h - e * g;
        float det = a * A + b * Bc + c * C;
        float id = 1.0f / det;
        S.Iinv[0] = A * id;            S.Iinv[1] = (c * h - b * i) * id;  S.Iinv[2] = (b * f - c * e) * id;
        S.Iinv[3] = Bc * id;           S.Iinv[4] = (a * i - c * g) * id;  S.Iinv[5] = (c * d - a * f) * id;
        S.Iinv[6] = C * id;            S.Iinv[7] = (b * g - a * h) * id;  S.Iinv[8] = (a * e - b * d) * id;
#pragma unroll
        for (int k = 0; k < 9; k++) S.Im[k] = Imat_g[k];
    }

    if (tid < BT) {
        const int row = tid;
        const size_t bidx = (size_t)blockIdx.x * BT + row;
#pragma unroll
        for (int s = 0; s < 12; s++) {
            float v = x_t[bidx * 12 + s];
            S.x[row][s] = v;
            outX[bidx * 12 * T + (size_t)s * T + 0] = v;
        }
    }
    __syncthreads();

    // per-thread copies of I and I^-1 for RK4 threads
    float ImR[9], IvR[9];
    if (tid < BT) {
#pragma unroll
        for (int k = 0; k < 9; k++) { ImR[k] = S.Im[k]; IvR[k] = S.Iinv[k]; }
    }

    for (int t = 0; t < steps; t++) {
        // ---- build MLP input, column-major: in[k*ST + row] ----
        if (tid < BT) {
            const int row = tid;
            const size_t bidx = (size_t)blockIdx.x * BT + row;
            S.in[0 * ST + row] = S.x[row][0] * 1.2732395447351628f;
            S.in[1 * ST + row] = S.x[row][1] * 0.5f;
            S.in[2 * ST + row] = S.x[row][2] * 1.2732395447351628f;
            S.in[3 * ST + row] = S.x[row][3] * 0.1f;
            S.in[4 * ST + row] = S.x[row][4] * 0.016666666666666666f;
            S.in[5 * ST + row] = S.x[row][5] * 0.016666666666666666f;
#pragma unroll
            for (int s = 6; s < 12; s++) S.in[s * ST + row] = 0.f;
#pragma unroll
            for (int a = 0; a < 4; a++)
                S.in[(12 + a) * ST + row] = (act[(bidx * 4 + a) * T + (t + 1)] - 1500.0f) / 500.0f;
        }
        __syncthreads();

        layer_col<16>(S, S.in, S.hA, W0, b0, tx, kh);
        layer_col<HD>(S, S.hA, S.hB, W1, b1, tx, kh);
        layer_col<HD>(S, S.hB, S.hA, W2, b2, tx, kh);

        // ---- layer 3: only output cols 0..2 used (moments are zero) ----
        // hA is column-major: hA[c*ST + row]
        if (tid < 96) {
            const int o = tid >> 1;          // 0..47
            const int half = tid & 1;
            const int row = o / 3;
            const int cc = o - row * 3;
            const float* hp = S.hA + (half * 256) * ST + row;
            const float* wp = W3 + (half * 256) * 6 + cc;
            float s = 0.f;
#pragma unroll 8
            for (int k = 0; k < 256; k++) s = fmaf(hp[k * ST], wp[k * 6], s);
            S.part[tid] = s;
        }
        __syncthreads();
        if (tid < 48) {
            const int row = tid / 3;
            const int cc = tid - row * 3;
            S.fn[row][cc] = S.part[2 * tid] + S.part[2 * tid + 1] + b3[cc];
        }
        __syncthreads();

        // ---- forces + RK4 + outputs ----
        if (tid < BT) {
            const int row = tid;
            const size_t bidx = (size_t)blockIdx.x * BT + row;
            const float F0 = S.fn[row][0] - 0.5f;
            const float F1 = S.fn[row][1] * (-0.4f) - 10.0f;
            const float F2 = S.fn[row][2] * 0.2f - 0.1f;

            float* fo = outF + bidx * 6 * steps + t;
            fo[0 * steps] = F0;
            fo[1 * steps] = F1;
            fo[2 * steps] = F2;
            fo[3 * steps] = 0.f;
            fo[4 * steps] = 0.f;
            fo[5 * steps] = 0.f;

            float xx[12];
#pragma unroll
            for (int s = 0; s < 12; s++) xx[s] = S.x[row][s];
            float k1[12], k2[12], k3[12], k4[12], tm[12];
            derivs(xx, F0, F1, F2, ImR, IvR, k1);
#pragma unroll
            for (int s = 0; s < 12; s++) tm[s] = xx[s] + 0.005f * k1[s];
            derivs(tm, F0, F1, F2, ImR, IvR, k2);
#pragma unroll
            for (int s = 0; s < 12; s++) tm[s] = xx[s] + 0.005f * k2[s];
            derivs(tm, F0, F1, F2, ImR, IvR, k3);
#pragma unroll
            for (int s = 0; s < 12; s++) tm[s] = xx[s] + 0.01f * k3[s];
            derivs(tm, F0, F1, F2, ImR, IvR, k4);
            const float w6 = (float)(0.01 / 6.0);
#pragma unroll
            for (int s = 0; s < 12; s++)
                xx[s] = xx[s] + w6 * (k1[s] + 2.f * k2[s] + 2.f * k3[s] + k4[s]);

            float* xo = outX + bidx * 12 * T + (t + 1);
#pragma unroll
            for (int s = 0; s < 12; s++) {
                S.x[row][s] = xx[s];
                xo[(size_t)s * T] = xx[s];
            }
        }
        __syncthreads();
    }
}

extern "C" void kernel_launch(void* const* d_in, const int* in_sizes, int n_in,
                              void* d_out, int out_size) {
    // metadata order follows setup_inputs() dict insertion order:
    // 0: x_t, 1: act_inps, 2: I_mat, 3: seq_len, 4..11: W0,b0,W1,b1,W2,b2,W3,b3
    const float* x_t = (const float*)d_in[0];
    const float* act = (const float*)d_in[1];
    const float* Im  = (const float*)d_in[2];
    const int* seqp  = (const int*)d_in[3];
    const float* W0  = (const float*)d_in[4];
    const float* b0  = (const float*)d_in[5];
    const float* W1  = (const float*)d_in[6];
    const float* b1  = (const float*)d_in[7];
    const float* W2  = (const float*)d_in[8];
    const float* b2  = (const float*)d_in[9];
    const float* W3  = (const float*)d_in[10];
    const float* b3  = (const float*)d_in[11];

    const int Bn = in_sizes[0] / 12;
    const int grid = Bn / BT;
    const size_t sm = sizeof(Smem);

    cudaFuncSetAttribute(wm_rollout, cudaFuncAttributeMaxDynamicSharedMemorySize, (int)sm);
    wm_rollout<<<grid, NTHREADS, sm>>>(x_t, act, Im, W0, b0, W1, b1, W2, b2, W3, b3,
                                       seqp, (float*)d_out, Bn);
}

// round 6
// speedup vs baseline: 1.2779x; 1.2779x over previous
#include <cuda_runtime.h>
#include <math.h>

#define NTHREADS 512
#define BT 16
#define HD 512
#define ST 20   // column stride (floats) for column-major activations; 80B keeps 16B alignment

typedef unsigned long long ull;

struct Smem {
    float hA[HD * ST];   // column-major: hA[c*ST + row]
    float hB[HD * ST];
    float in[16 * ST];   // column-major MLP input
    float x[BT][12];
    float fn[BT][3];
    float part[96];
    float Im[9];
    float Iinv[9];
};

__device__ __forceinline__ float leaky(float v) { return v >= 0.f ? v : 0.01f * v; }

// packed f32x2 ops (sm_100+)
__device__ __forceinline__ ull fma2(ull a, ull b, ull c) {
    ull d;
    asm("fma.rn.f32x2 %0, %1, %2, %3;" : "=l"(d) : "l"(a), "l"(b), "l"(c));
    return d;
}
__device__ __forceinline__ ull pack2(float x) {
    ull r;
    asm("mov.b64 %0, {%1, %1};" : "=l"(r) : "f"(x));
    return r;
}
__device__ __forceinline__ float2 unpack2(ull v) {
    float2 f;
    asm("mov.b64 {%0, %1}, %2;" : "=f"(f.x), "=f"(f.y) : "l"(v));
    return f;
}

// 512 -> 512 layer, col-major activations, software-pipelined W loads.
// Thread (ty in {0,1}, tx in [0,256)): rows ty*8..+7, cols {2tx, 2tx+1}.
// Per k: 1x LDG.64 (W col pair, prefetched 8 deep), 2x pack, 2x LDS.128, 8x FFMA2.
__device__ __forceinline__ void layer512(const float* __restrict__ si,
                                         float* __restrict__ so,
                                         const float* __restrict__ W,
                                         const float* __restrict__ bv,
                                         int ty, int tx) {
    const int r0 = ty * 8;
    const int c0 = tx * 2;
    ull acc[4][2];
#pragma unroll
    for (int p = 0; p < 4; p++) { acc[p][0] = 0ULL; acc[p][1] = 0ULL; }

    const float2* W2 = reinterpret_cast<const float2*>(W);   // [k][256] float2
    float2 wc[8], wn[8];
#pragma unroll
    for (int u = 0; u < 8; u++) wc[u] = W2[u * 256 + tx];

    const float* ap = si + r0;
    for (int k0 = 0; k0 < HD; k0 += 8) {
        const bool pf = (k0 + 8) < HD;
        const float2* wpn = W2 + (k0 + 8) * 256 + tx;
#pragma unroll
        for (int u = 0; u < 8; u++)
            if (pf) wn[u] = wpn[u * 256];
#pragma unroll
        for (int u = 0; u < 8; u++) {
            ull w0 = pack2(wc[u].x);
            ull w1 = pack2(wc[u].y);
            const float* a = ap + (k0 + u) * ST;
            ulonglong2 aA = *reinterpret_cast<const ulonglong2*>(a);
            ulonglong2 aB = *reinterpret_cast<const ulonglong2*>(a + 4);
            acc[0][0] = fma2(aA.x, w0, acc[0][0]);
            acc[0][1] = fma2(aA.x, w1, acc[0][1]);
            acc[1][0] = fma2(aA.y, w0, acc[1][0]);
            acc[1][1] = fma2(aA.y, w1, acc[1][1]);
            acc[2][0] = fma2(aB.x, w0, acc[2][0]);
            acc[2][1] = fma2(aB.x, w1, acc[2][1]);
            acc[3][0] = fma2(aB.y, w0, acc[3][0]);
            acc[3][1] = fma2(aB.y, w1, acc[3][1]);
        }
#pragma unroll
        for (int u = 0; u < 8; u++) wc[u] = wn[u];
    }

    const float2 bb = *reinterpret_cast<const float2*>(bv + c0);
#pragma unroll
    for (int c = 0; c < 2; c++) {
        const float b = (c == 0) ? bb.x : bb.y;
        float2 v0 = unpack2(acc[0][c]);
        float2 v1 = unpack2(acc[1][c]);
        float2 v2 = unpack2(acc[2][c]);
        float2 v3 = unpack2(acc[3][c]);
        float4 o0, o1;
        o0.x = leaky(v0.x + b); o0.y = leaky(v0.y + b);
        o0.z = leaky(v1.x + b); o0.w = leaky(v1.y + b);
        o1.x = leaky(v2.x + b); o1.y = leaky(v2.y + b);
        o1.z = leaky(v3.x + b); o1.w = leaky(v3.y + b);
        float* op = so + (c0 + c) * ST + r0;
        *reinterpret_cast<float4*>(op) = o0;
        *reinterpret_cast<float4*>(op + 4) = o1;
    }
}

// 16 -> 512 layer (same mapping, K=16, no pipeline needed)
__device__ __forceinline__ void layer16(const float* __restrict__ si,
                                        float* __restrict__ so,
                                        const float* __restrict__ W,
                                        const float* __restrict__ bv,
                                        int ty, int tx) {
    const int r0 = ty * 8;
    const int c0 = tx * 2;
    ull acc[4][2];
#pragma unroll
    for (int p = 0; p < 4; p++) { acc[p][0] = 0ULL; acc[p][1] = 0ULL; }

    const float2* W2 = reinterpret_cast<const float2*>(W);
    const float* ap = si + r0;
#pragma unroll
    for (int k = 0; k < 16; k++) {
        float2 w = W2[k * 256 + tx];
        ull w0 = pack2(w.x);
        ull w1 = pack2(w.y);
        const float* a = ap + k * ST;
        ulonglong2 aA = *reinterpret_cast<const ulonglong2*>(a);
        ulonglong2 aB = *reinterpret_cast<const ulonglong2*>(a + 4);
        acc[0][0] = fma2(aA.x, w0, acc[0][0]);
        acc[0][1] = fma2(aA.x, w1, acc[0][1]);
        acc[1][0] = fma2(aA.y, w0, acc[1][0]);
        acc[1][1] = fma2(aA.y, w1, acc[1][1]);
        acc[2][0] = fma2(aB.x, w0, acc[2][0]);
        acc[2][1] = fma2(aB.x, w1, acc[2][1]);
        acc[3][0] = fma2(aB.y, w0, acc[3][0]);
        acc[3][1] = fma2(aB.y, w1, acc[3][1]);
    }

    const float2 bb = *reinterpret_cast<const float2*>(bv + c0);
#pragma unroll
    for (int c = 0; c < 2; c++) {
        const float b = (c == 0) ? bb.x : bb.y;
        float2 v0 = unpack2(acc[0][c]);
        float2 v1 = unpack2(acc[1][c]);
        float2 v2 = unpack2(acc[2][c]);
        float2 v3 = unpack2(acc[3][c]);
        float4 o0, o1;
        o0.x = leaky(v0.x + b); o0.y = leaky(v0.y + b);
        o0.z = leaky(v1.x + b); o0.w = leaky(v1.y + b);
        o1.x = leaky(v2.x + b); o1.y = leaky(v2.y + b);
        o1.z = leaky(v3.x + b); o1.w = leaky(v3.y + b);
        float* op = so + (c0 + c) * ST + r0;
        *reinterpret_cast<float4*>(op) = o0;
        *reinterpret_cast<float4*>(op + 4) = o1;
    }
}

// Rigid-body derivatives, M (moments) == 0.
__device__ __forceinline__ void derivs(const float x[12], float F0, float F1, float F2,
                                       const float Im[9], const float Iv[9], float dx[12]) {
    float V0 = x[3], V1 = x[4], V2 = x[5];
    float phi = x[6], th = x[7], ps = x[8];
    float w0 = x[9], w1 = x[10], w2 = x[11];
    float cph = cosf(phi), sph = sinf(phi);
    float cth = cosf(th), sth = sinf(th);
    float cps = cosf(ps), sps = sinf(ps);

    dx[0] = (cth * cps) * V0 + (sph * sth * cps - cph * sps) * V1 + (cph * sth * cps + sph * sps) * V2;
    dx[1] = (cth * sps) * V0 + (sph * sth * sps + cph * cps) * V1 + (cph * sth * sps - sph * cps) * V2;
    dx[2] = (-sth) * V0 + (sph * cth) * V1 + (cph * cth) * V2;

    dx[3] = F0 / 1.5f - (w1 * V2 - w2 * V1);
    dx[4] = F1 / 1.5f - (w2 * V0 - w0 * V2);
    dx[5] = F2 / 1.5f - (w0 * V1 - w1 * V0);

    float tth = tanf(th);
    float cthc = fmaxf(cth, 1e-6f);
    float ic = 1.0f / cthc;
    dx[6] = w0 + sph * tth * w1 + cph * tth * w2;
    dx[7] = cph * w1 - sph * w2;
    dx[8] = (sph * ic) * w1 + (cph * ic) * w2;

    float Iw0 = Im[0] * w0 + Im[1] * w1 + Im[2] * w2;
    float Iw1 = Im[3] * w0 + Im[4] * w1 + Im[5] * w2;
    float Iw2 = Im[6] * w0 + Im[7] * w1 + Im[8] * w2;
    float c0 = w1 * Iw2 - w2 * Iw1;
    float c1 = w2 * Iw0 - w0 * Iw2;
    float c2 = w0 * Iw1 - w1 * Iw0;
    dx[9]  = -(Iv[0] * c0 + Iv[1] * c1 + Iv[2] * c2);
    dx[10] = -(Iv[3] * c0 + Iv[4] * c1 + Iv[5] * c2);
    dx[11] = -(Iv[6] * c0 + Iv[7] * c1 + Iv[8] * c2);
}

extern "C" __global__ void __launch_bounds__(NTHREADS, 1)
wm_rollout(const float* __restrict__ x_t, const float* __restrict__ act,
           const float* __restrict__ Imat_g,
           const float* __restrict__ W0, const float* __restrict__ b0,
           const float* __restrict__ W1, const float* __restrict__ b1,
           const float* __restrict__ W2, const float* __restrict__ b2,
           const float* __restrict__ W3, const float* __restrict__ b3,
           const int* __restrict__ seqp, float* __restrict__ out, int Bn) {
    extern __shared__ char smc[];
    Smem& S = *reinterpret_cast<Smem*>(smc);
    const int tid = threadIdx.x;
    const int ty = tid >> 8;       // 0..1
    const int tx = tid & 255;      // 0..255

    const int T = seqp[0];
    const int steps = T - 1;
    float* outF = out;                                   // [B, 6, T-1]
    float* outX = out + (size_t)Bn * 6 * steps;          // [B, 12, T]

    if (tid == 0) {
        float a = Imat_g[0], b = Imat_g[1], c = Imat_g[2];
        float d = Imat_g[3], e = Imat_g[4], f = Imat_g[5];
        float g = Imat_g[6], h = Imat_g[7], i = Imat_g[8];
        float A = e * i - f * h;
        float Bc = -(d * i - f * g);
        float C = d * h - e * g;
        float det = a * A + b * Bc + c * C;
        float id = 1.0f / det;
        S.Iinv[0] = A * id;            S.Iinv[1] = (c * h - b * i) * id;  S.Iinv[2] = (b * f - c * e) * id;
        S.Iinv[3] = Bc * id;           S.Iinv[4] = (a * i - c * g) * id;  S.Iinv[5] = (c * d - a * f) * id;
        S.Iinv[6] = C * id;            S.Iinv[7] = (b * g - a * h) * id;  S.Iinv[8] = (a * e - b * d) * id;
#pragma unroll
        for (int k = 0; k < 9; k++) S.Im[k] = Imat_g[k];
    }

    if (tid < BT) {
        const int row = tid;
        const size_t bidx = (size_t)blockIdx.x * BT + row;
#pragma unroll
        for (int s = 0; s < 12; s++) {
            float v = x_t[bidx * 12 + s];
            S.x[row][s] = v;
            outX[bidx * 12 * T + (size_t)s * T + 0] = v;
        }
    }
    __syncthreads();

    // per-thread copies of I and I^-1 for RK4 threads
    float ImR[9], IvR[9];
    if (tid < BT) {
#pragma unroll
        for (int k = 0; k < 9; k++) { ImR[k] = S.Im[k]; IvR[k] = S.Iinv[k]; }
    }

    for (int t = 0; t < steps; t++) {
        // ---- build MLP input, column-major: in[k*ST + row] ----
        if (tid < BT) {
            const int row = tid;
            const size_t bidx = (size_t)blockIdx.x * BT + row;
            S.in[0 * ST + row] = S.x[row][0] * 1.2732395447351628f;
            S.in[1 * ST + row] = S.x[row][1] * 0.5f;
            S.in[2 * ST + row] = S.x[row][2] * 1.2732395447351628f;
            S.in[3 * ST + row] = S.x[row][3] * 0.1f;
            S.in[4 * ST + row] = S.x[row][4] * 0.016666666666666666f;
            S.in[5 * ST + row] = S.x[row][5] * 0.016666666666666666f;
#pragma unroll
            for (int s = 6; s < 12; s++) S.in[s * ST + row] = 0.f;
#pragma unroll
            for (int a = 0; a < 4; a++)
                S.in[(12 + a) * ST + row] = (act[(bidx * 4 + a) * T + (t + 1)] - 1500.0f) / 500.0f;
        }
        __syncthreads();

        layer16(S.in, S.hA, W0, b0, ty, tx);
        __syncthreads();
        layer512(S.hA, S.hB, W1, b1, ty, tx);
        __syncthreads();
        layer512(S.hB, S.hA, W2, b2, ty, tx);
        __syncthreads();

        // ---- layer 3: only output cols 0..2 used (moments are zero) ----
        // hA is column-major: hA[c*ST + row]
        if (tid < 96) {
            const int o = tid >> 1;          // 0..47
            const int half = tid & 1;
            const int row = o / 3;
            const int cc = o - row * 3;
            const float* hp = S.hA + (half * 256) * ST + row;
            const float* wp = W3 + (half * 256) * 6 + cc;
            float s = 0.f;
#pragma unroll 8
            for (int k = 0; k < 256; k++) s = fmaf(hp[k * ST], wp[k * 6], s);
            S.part[tid] = s;
        }
        __syncthreads();
        if (tid < 48) {
            const int row = tid / 3;
            const int cc = tid - row * 3;
            S.fn[row][cc] = S.part[2 * tid] + S.part[2 * tid + 1] + b3[cc];
        }
        __syncthreads();

        // ---- forces + RK4 + outputs ----
        if (tid < BT) {
            const int row = tid;
            const size_t bidx = (size_t)blockIdx.x * BT + row;
            const float F0 = S.fn[row][0] - 0.5f;
            const float F1 = S.fn[row][1] * (-0.4f) - 10.0f;
            const float F2 = S.fn[row][2] * 0.2f - 0.1f;

            float* fo = outF + bidx * 6 * steps + t;
            fo[0 * steps] = F0;
            fo[1 * steps] = F1;
            fo[2 * steps] = F2;
            fo[3 * steps] = 0.f;
            fo[4 * steps] = 0.f;
            fo[5 * steps] = 0.f;

            float xx[12];
#pragma unroll
            for (int s = 0; s < 12; s++) xx[s] = S.x[row][s];
            float k1[12], k2[12], k3[12], k4[12], tm[12];
            derivs(xx, F0, F1, F2, ImR, IvR, k1);
#pragma unroll
            for (int s = 0; s < 12; s++) tm[s] = xx[s] + 0.005f * k1[s];
            derivs(tm, F0, F1, F2, ImR, IvR, k2);
#pragma unroll
            for (int s = 0; s < 12; s++) tm[s] = xx[s] + 0.005f * k2[s];
            derivs(tm, F0, F1, F2, ImR, IvR, k3);
#pragma unroll
            for (int s = 0; s < 12; s++) tm[s] = xx[s] + 0.01f * k3[s];
            derivs(tm, F0, F1, F2, ImR, IvR, k4);
            const float w6 = (float)(0.01 / 6.0);
#pragma unroll
            for (int s = 0; s < 12; s++)
                xx[s] = xx[s] + w6 * (k1[s] + 2.f * k2[s] + 2.f * k3[s] + k4[s]);

            float* xo = outX + bidx * 12 * T + (t + 1);
#pragma unroll
            for (int s = 0; s < 12; s++) {
                S.x[row][s] = xx[s];
                xo[(size_t)s * T] = xx[s];
            }
        }
        __syncthreads();
    }
}

extern "C" void kernel_launch(void* const* d_in, const int* in_sizes, int n_in,
                              void* d_out, int out_size) {
    // metadata order follows setup_inputs() dict insertion order:
    // 0: x_t, 1: act_inps, 2: I_mat, 3: seq_len, 4..11: W0,b0,W1,b1,W2,b2,W3,b3
    const float* x_t = (const float*)d_in[0];
    const float* act = (const float*)d_in[1];
    const float* Im  = (const float*)d_in[2];
    const int* seqp  = (const int*)d_in[3];
    const float* W0  = (const float*)d_in[4];
    const float* b0  = (const float*)d_in[5];
    const float* W1  = (const float*)d_in[6];
    const float* b1  = (const float*)d_in[7];
    const float* W2  = (const float*)d_in[8];
    const float* b2  = (const float*)d_in[9];
    const float* W3  = (const float*)d_in[10];
    const float* b3  = (const float*)d_in[11];

    const int Bn = in_sizes[0] / 12;
    const int grid = Bn / BT;
    const size_t sm = sizeof(Smem);

    cudaFuncSetAttribute(wm_rollout, cudaFuncAttributeMaxDynamicSharedMemorySize, (int)sm);
    wm_rollout<<<grid, NTHREADS, sm>>>(x_t, act, Im, W0, b0, W1, b1, W2, b2, W3, b3,
                                       seqp, (float*)d_out, Bn);
}

// round 7
// speedup vs baseline: 1.2900x; 1.0094x over previous
#include <cuda_runtime.h>
#include <math.h>

#define NTHREADS 512
#define BT 16
#define HD 512
#define ST 20   // column stride (floats) for column-major activations; 80B keeps 16B alignment

typedef unsigned long long ull;

struct Smem {
    float hA[HD * ST];   // column-major: hA[c*ST + row]
    float hB[HD * ST];
    float in[16 * ST];   // column-major MLP input
    float x[BT][12];
    float fn[BT][3];
    float part[48][8];   // L3 partials
    float Im[9];
    float Iinv[9];
};

__device__ __forceinline__ float leaky(float v) { return v >= 0.f ? v : 0.01f * v; }

// packed f32x2 ops (sm_100+)
__device__ __forceinline__ ull fma2(ull a, ull b, ull c) {
    ull d;
    asm("fma.rn.f32x2 %0, %1, %2, %3;" : "=l"(d) : "l"(a), "l"(b), "l"(c));
    return d;
}
__device__ __forceinline__ ull pack2(float x) {
    ull r;
    asm("mov.b64 %0, {%1, %1};" : "=l"(r) : "f"(x));
    return r;
}
__device__ __forceinline__ float2 unpack2(ull v) {
    float2 f;
    asm("mov.b64 {%0, %1}, %2;" : "=f"(f.x), "=f"(f.y) : "l"(v));
    return f;
}

// 512 -> 512 layer, col-major activations, software-pipelined W + batched LDS windows.
// Thread (ty in {0,1}, tx in [0,256)): rows ty*8..+7, cols {2tx, 2tx+1}.
__device__ __forceinline__ void layer512(const float* __restrict__ si,
                                         float* __restrict__ so,
                                         const float* __restrict__ W,
                                         const float* __restrict__ bv,
                                         int ty, int tx) {
    const int r0 = ty * 8;
    const int c0 = tx * 2;
    ull acc[4][2];
#pragma unroll
    for (int p = 0; p < 4; p++) { acc[p][0] = 0ULL; acc[p][1] = 0ULL; }

    const float2* W2 = reinterpret_cast<const float2*>(W);   // [k][256] float2
    float2 wc[8], wn[8];
#pragma unroll
    for (int u = 0; u < 8; u++) wc[u] = W2[u * 256 + tx];

    const float* ap = si + r0;
    for (int k0 = 0; k0 < HD; k0 += 8) {
        // batch-issue all activation LDS for this window (16 outstanding LDS.128)
        ulonglong2 aA[8], aB[8];
#pragma unroll
        for (int u = 0; u < 8; u++) {
            const float* a = ap + (k0 + u) * ST;
            aA[u] = *reinterpret_cast<const ulonglong2*>(a);
            aB[u] = *reinterpret_cast<const ulonglong2*>(a + 4);
        }
        // prefetch next W window (8 outstanding LDG.64)
        const bool pf = (k0 + 8) < HD;
        const float2* wpn = W2 + (k0 + 8) * 256 + tx;
#pragma unroll
        for (int u = 0; u < 8; u++)
            if (pf) wn[u] = wpn[u * 256];
        // hoist W packs for the window
        ull w0[8], w1[8];
#pragma unroll
        for (int u = 0; u < 8; u++) {
            w0[u] = pack2(wc[u].x);
            w1[u] = pack2(wc[u].y);
        }
        // pure-FMA body
#pragma unroll
        for (int u = 0; u < 8; u++) {
            acc[0][0] = fma2(aA[u].x, w0[u], acc[0][0]);
            acc[0][1] = fma2(aA[u].x, w1[u], acc[0][1]);
            acc[1][0] = fma2(aA[u].y, w0[u], acc[1][0]);
            acc[1][1] = fma2(aA[u].y, w1[u], acc[1][1]);
            acc[2][0] = fma2(aB[u].x, w0[u], acc[2][0]);
            acc[2][1] = fma2(aB[u].x, w1[u], acc[2][1]);
            acc[3][0] = fma2(aB[u].y, w0[u], acc[3][0]);
            acc[3][1] = fma2(aB[u].y, w1[u], acc[3][1]);
        }
#pragma unroll
        for (int u = 0; u < 8; u++) wc[u] = wn[u];
    }

    const float2 bb = *reinterpret_cast<const float2*>(bv + c0);
#pragma unroll
    for (int c = 0; c < 2; c++) {
        const float b = (c == 0) ? bb.x : bb.y;
        float2 v0 = unpack2(acc[0][c]);
        float2 v1 = unpack2(acc[1][c]);
        float2 v2 = unpack2(acc[2][c]);
        float2 v3 = unpack2(acc[3][c]);
        float4 o0, o1;
        o0.x = leaky(v0.x + b); o0.y = leaky(v0.y + b);
        o0.z = leaky(v1.x + b); o0.w = leaky(v1.y + b);
        o1.x = leaky(v2.x + b); o1.y = leaky(v2.y + b);
        o1.z = leaky(v3.x + b); o1.w = leaky(v3.y + b);
        float* op = so + (c0 + c) * ST + r0;
        *reinterpret_cast<float4*>(op) = o0;
        *reinterpret_cast<float4*>(op + 4) = o1;
    }
}

// 16 -> 512 layer (same mapping, K=16)
__device__ __forceinline__ void layer16(const float* __restrict__ si,
                                        float* __restrict__ so,
                                        const float* __restrict__ W,
                                        const float* __restrict__ bv,
                                        int ty, int tx) {
    const int r0 = ty * 8;
    const int c0 = tx * 2;
    ull acc[4][2];
#pragma unroll
    for (int p = 0; p < 4; p++) { acc[p][0] = 0ULL; acc[p][1] = 0ULL; }

    const float2* W2 = reinterpret_cast<const float2*>(W);
    const float* ap = si + r0;
#pragma unroll
    for (int k = 0; k < 16; k++) {
        float2 w = W2[k * 256 + tx];
        ull w0 = pack2(w.x);
        ull w1 = pack2(w.y);
        const float* a = ap + k * ST;
        ulonglong2 aA = *reinterpret_cast<const ulonglong2*>(a);
        ulonglong2 aB = *reinterpret_cast<const ulonglong2*>(a + 4);
        acc[0][0] = fma2(aA.x, w0, acc[0][0]);
        acc[0][1] = fma2(aA.x, w1, acc[0][1]);
        acc[1][0] = fma2(aA.y, w0, acc[1][0]);
        acc[1][1] = fma2(aA.y, w1, acc[1][1]);
        acc[2][0] = fma2(aB.x, w0, acc[2][0]);
        acc[2][1] = fma2(aB.x, w1, acc[2][1]);
        acc[3][0] = fma2(aB.y, w0, acc[3][0]);
        acc[3][1] = fma2(aB.y, w1, acc[3][1]);
    }

    const float2 bb = *reinterpret_cast<const float2*>(bv + c0);
#pragma unroll
    for (int c = 0; c < 2; c++) {
        const float b = (c == 0) ? bb.x : bb.y;
        float2 v0 = unpack2(acc[0][c]);
        float2 v1 = unpack2(acc[1][c]);
        float2 v2 = unpack2(acc[2][c]);
        float2 v3 = unpack2(acc[3][c]);
        float4 o0, o1;
        o0.x = leaky(v0.x + b); o0.y = leaky(v0.y + b);
        o0.z = leaky(v1.x + b); o0.w = leaky(v1.y + b);
        o1.x = leaky(v2.x + b); o1.y = leaky(v2.y + b);
        o1.z = leaky(v3.x + b); o1.w = leaky(v3.y + b);
        float* op = so + (c0 + c) * ST + r0;
        *reinterpret_cast<float4*>(op) = o0;
        *reinterpret_cast<float4*>(op + 4) = o1;
    }
}

// Rigid-body derivatives, M (moments) == 0.
__device__ __forceinline__ void derivs(const float x[12], float F0, float F1, float F2,
                                       const float Im[9], const float Iv[9], float dx[12]) {
    float V0 = x[3], V1 = x[4], V2 = x[5];
    float phi = x[6], th = x[7], ps = x[8];
    float w0 = x[9], w1 = x[10], w2 = x[11];
    float cph = cosf(phi), sph = sinf(phi);
    float cth = cosf(th), sth = sinf(th);
    float cps = cosf(ps), sps = sinf(ps);

    dx[0] = (cth * cps) * V0 + (sph * sth * cps - cph * sps) * V1 + (cph * sth * cps + sph * sps) * V2;
    dx[1] = (cth * sps) * V0 + (sph * sth * sps + cph * cps) * V1 + (cph * sth * sps - sph * cps) * V2;
    dx[2] = (-sth) * V0 + (sph * cth) * V1 + (cph * cth) * V2;

    dx[3] = F0 / 1.5f - (w1 * V2 - w2 * V1);
    dx[4] = F1 / 1.5f - (w2 * V0 - w0 * V2);
    dx[5] = F2 / 1.5f - (w0 * V1 - w1 * V0);

    float tth = tanf(th);
    float cthc = fmaxf(cth, 1e-6f);
    float ic = 1.0f / cthc;
    dx[6] = w0 + sph * tth * w1 + cph * tth * w2;
    dx[7] = cph * w1 - sph * w2;
    dx[8] = (sph * ic) * w1 + (cph * ic) * w2;

    float Iw0 = Im[0] * w0 + Im[1] * w1 + Im[2] * w2;
    float Iw1 = Im[3] * w0 + Im[4] * w1 + Im[5] * w2;
    float Iw2 = Im[6] * w0 + Im[7] * w1 + Im[8] * w2;
    float c0 = w1 * Iw2 - w2 * Iw1;
    float c1 = w2 * Iw0 - w0 * Iw2;
    float c2 = w0 * Iw1 - w1 * Iw0;
    dx[9]  = -(Iv[0] * c0 + Iv[1] * c1 + Iv[2] * c2);
    dx[10] = -(Iv[3] * c0 + Iv[4] * c1 + Iv[5] * c2);
    dx[11] = -(Iv[6] * c0 + Iv[7] * c1 + Iv[8] * c2);
}

extern "C" __global__ void __launch_bounds__(NTHREADS, 1)
wm_rollout(const float* __restrict__ x_t, const float* __restrict__ act,
           const float* __restrict__ Imat_g,
           const float* __restrict__ W0, const float* __restrict__ b0,
           const float* __restrict__ W1, const float* __restrict__ b1,
           const float* __restrict__ W2, const float* __restrict__ b2,
           const float* __restrict__ W3, const float* __restrict__ b3,
           const int* __restrict__ seqp, float* __restrict__ out, int Bn) {
    extern __shared__ char smc[];
    Smem& S = *reinterpret_cast<Smem*>(smc);
    const int tid = threadIdx.x;
    const int ty = tid >> 8;       // 0..1
    const int tx = tid & 255;      // 0..255

    const int T = seqp[0];
    const int steps = T - 1;
    float* outF = out;                                   // [B, 6, T-1]
    float* outX = out + (size_t)Bn * 6 * steps;          // [B, 12, T]

    if (tid == 0) {
        float a = Imat_g[0], b = Imat_g[1], c = Imat_g[2];
        float d = Imat_g[3], e = Imat_g[4], f = Imat_g[5];
        float g = Imat_g[6], h = Imat_g[7], i = Imat_g[8];
        float A = e * i - f * h;
        float Bc = -(d * i - f * g);
        float C = d * h - e * g;
        float det = a * A + b * Bc + c * C;
        float id = 1.0f / det;
        S.Iinv[0] = A * id;            S.Iinv[1] = (c * h - b * i) * id;  S.Iinv[2] = (b * f - c * e) * id;
        S.Iinv[3] = Bc * id;           S.Iinv[4] = (a * i - c * g) * id;  S.Iinv[5] = (c * d - a * f) * id;
        S.Iinv[6] = C * id;            S.Iinv[7] = (b * g - a * h) * id;  S.Iinv[8] = (a * e - b * d) * id;
#pragma unroll
        for (int k = 0; k < 9; k++) S.Im[k] = Imat_g[k];
    }

    if (tid < BT) {
        const int row = tid;
        const size_t bidx = (size_t)blockIdx.x * BT + row;
#pragma unroll
        for (int s = 0; s < 12; s++) {
            float v = x_t[bidx * 12 + s];
            S.x[row][s] = v;
            outX[bidx * 12 * T + (size_t)s * T + 0] = v;
        }
    }
    __syncthreads();

    // per-thread copies of I and I^-1 for RK4 threads
    float ImR[9], IvR[9];
    if (tid < BT) {
#pragma unroll
        for (int k = 0; k < 9; k++) { ImR[k] = S.Im[k]; IvR[k] = S.Iinv[k]; }
    }

    for (int t = 0; t < steps; t++) {
        // ---- build MLP input, column-major: in[k*ST + row] ----
        if (tid < BT) {
            const int row = tid;
            const size_t bidx = (size_t)blockIdx.x * BT + row;
            S.in[0 * ST + row] = S.x[row][0] * 1.2732395447351628f;
            S.in[1 * ST + row] = S.x[row][1] * 0.5f;
            S.in[2 * ST + row] = S.x[row][2] * 1.2732395447351628f;
            S.in[3 * ST + row] = S.x[row][3] * 0.1f;
            S.in[4 * ST + row] = S.x[row][4] * 0.016666666666666666f;
            S.in[5 * ST + row] = S.x[row][5] * 0.016666666666666666f;
#pragma unroll
            for (int s = 6; s < 12; s++) S.in[s * ST + row] = 0.f;
#pragma unroll
            for (int a = 0; a < 4; a++)
                S.in[(12 + a) * ST + row] = (act[(bidx * 4 + a) * T + (t + 1)] - 1500.0f) / 500.0f;
        }
        __syncthreads();

        layer16(S.in, S.hA, W0, b0, ty, tx);
        __syncthreads();
        layer512(S.hA, S.hB, W1, b1, ty, tx);
        __syncthreads();
        layer512(S.hB, S.hA, W2, b2, ty, tx);
        __syncthreads();

        // ---- layer 3 over 512 threads: 48 dots x 8 k-partials of 64 ----
        {
            const int o = tid >> 3;          // 0..63 (use 0..47)
            const int h = tid & 7;           // k-partial
            if (o < 48) {
                const int row = o / 3;
                const int cc = o - row * 3;
                const float* hp = S.hA + row;
                const float* wp = W3 + cc;
                float s = 0.f;
                const int kb = h * 64;
#pragma unroll 8
                for (int k = 0; k < 64; k++)
                    s = fmaf(hp[(kb + k) * ST], wp[(kb + k) * 6], s);
                S.part[o][h] = s;
            }
        }
        __syncthreads();
        if (tid < 48) {
            const int row = tid / 3;
            const int cc = tid - row * 3;
            const float* pp = S.part[tid];
            float s = ((pp[0] + pp[1]) + (pp[2] + pp[3])) + ((pp[4] + pp[5]) + (pp[6] + pp[7]));
            S.fn[row][cc] = s + b3[cc];
        }
        __syncthreads();

        // ---- forces + RK4 + outputs ----
        if (tid < BT) {
            const int row = tid;
            const size_t bidx = (size_t)blockIdx.x * BT + row;
            const float F0 = S.fn[row][0] - 0.5f;
            const float F1 = S.fn[row][1] * (-0.4f) - 10.0f;
            const float F2 = S.fn[row][2] * 0.2f - 0.1f;

            float* fo = outF + bidx * 6 * steps + t;
            fo[0 * steps] = F0;
            fo[1 * steps] = F1;
            fo[2 * steps] = F2;
            fo[3 * steps] = 0.f;
            fo[4 * steps] = 0.f;
            fo[5 * steps] = 0.f;

            float xx[12];
#pragma unroll
            for (int s = 0; s < 12; s++) xx[s] = S.x[row][s];
            float k1[12], k2[12], k3[12], k4[12], tm[12];
            derivs(xx, F0, F1, F2, ImR, IvR, k1);
#pragma unroll
            for (int s = 0; s < 12; s++) tm[s] = xx[s] + 0.005f * k1[s];
            derivs(tm, F0, F1, F2, ImR, IvR, k2);
#pragma unroll
            for (int s = 0; s < 12; s++) tm[s] = xx[s] + 0.005f * k2[s];
            derivs(tm, F0, F1, F2, ImR, IvR, k3);
#pragma unroll
            for (int s = 0; s < 12; s++) tm[s] = xx[s] + 0.01f * k3[s];
            derivs(tm, F0, F1, F2, ImR, IvR, k4);
            const float w6 = (float)(0.01 / 6.0);
#pragma unroll
            for (int s = 0; s < 12; s++)
                xx[s] = xx[s] + w6 * (k1[s] + 2.f * k2[s] + 2.f * k3[s] + k4[s]);

            float* xo = outX + bidx * 12 * T + (t + 1);
#pragma unroll
            for (int s = 0; s < 12; s++) {
                S.x[row][s] = xx[s];
                xo[(size_t)s * T] = xx[s];
            }
        }
        __syncthreads();
    }
}

extern "C" void kernel_launch(void* const* d_in, const int* in_sizes, int n_in,
                              void* d_out, int out_size) {
    // metadata order follows setup_inputs() dict insertion order:
    // 0: x_t, 1: act_inps, 2: I_mat, 3: seq_len, 4..11: W0,b0,W1,b1,W2,b2,W3,b3
    const float* x_t = (const float*)d_in[0];
    const float* act = (const float*)d_in[1];
    const float* Im  = (const float*)d_in[2];
    const int* seqp  = (const int*)d_in[3];
    const float* W0  = (const float*)d_in[4];
    const float* b0  = (const float*)d_in[5];
    const float* W1  = (const float*)d_in[6];
    const float* b1  = (const float*)d_in[7];
    const float* W2  = (const float*)d_in[8];
    const float* b2  = (const float*)d_in[9];
    const float* W3  = (const float*)d_in[10];
    const float* b3  = (const float*)d_in[11];

    const int Bn = in_sizes[0] / 12;
    const int grid = Bn / BT;
    const size_t sm = sizeof(Smem);

    cudaFuncSetAttribute(wm_rollout, cudaFuncAttributeMaxDynamicSharedMemorySize, (int)sm);
    wm_rollout<<<grid, NTHREADS, sm>>>(x_t, act, Im, W0, b0, W1, b1, W2, b2, W3, b3,
                                       seqp, (float*)d_out, Bn);
}